// round 3
// baseline (speedup 1.0000x reference)
#include <cuda_runtime.h>
#include <cuda_bf16.h>
#include <cstdint>

// Problem constants
#define BDIM 1024
#define DIN  64
#define DHID 128
#define BN_EPS 1e-5f

// Scratch (device globals; no allocations allowed)
__device__ float g_At[DHID * BDIM];   // A^T: [k][i] = b1[k] + sum_d x[i][d] W1[d][k]
__device__ float g_Ct[DHID * BDIM];   // C^T: [k][j] = sum_d x[j][d] W1[64+d][k]
__device__ float g_s[DHID];           // folded scale  gamma*rsigma*W2
__device__ float g_tpart[DHID];       // per-channel bias contribution

// ---------------------------------------------------------------------------
// Kernel 1 (fused): one block per channel k (128 blocks x 1024 threads).
//  - compute At[k][j], Ct[k][j] (thread j)
//  - register bitonic sort of Ct row, shfl suffix scans of c and c^2
//  - binary-search stats  ->  per-channel BN fold (g_s, g_tpart)
// ---------------------------------------------------------------------------
__global__ __launch_bounds__(1024) void channel_kernel(
    const float* __restrict__ x, const float* __restrict__ W1,
    const float* __restrict__ b1, const float* __restrict__ gamma,
    const float* __restrict__ beta, const float* __restrict__ W2)
{
    __shared__ float wcol[2 * DIN];
    __shared__ float sc[BDIM];
    __shared__ float ssf[BDIM + 2];
    __shared__ float ssf2[BDIM + 2];
    __shared__ float wr1[32];
    __shared__ float wr2[32];

    const int k = blockIdx.x;
    const int tid = threadIdx.x;
    const int lane = tid & 31;
    const int warp = tid >> 5;

    if (tid < 2 * DIN) wcol[tid] = W1[tid * DHID + k];
    __syncthreads();

    // --- dot products: a = b1 + x[j]·W1[:64,k], c = x[j]·W1[64:,k] ---
    float a = b1[k], c = 0.f;
    const float4* xr = (const float4*)(x + (size_t)tid * DIN);
#pragma unroll
    for (int d4 = 0; d4 < DIN / 4; d4++) {
        const float4 xv = xr[d4];
        const int d = d4 * 4;
        a = fmaf(xv.x, wcol[d + 0], a);  c = fmaf(xv.x, wcol[DIN + d + 0], c);
        a = fmaf(xv.y, wcol[d + 1], a);  c = fmaf(xv.y, wcol[DIN + d + 1], c);
        a = fmaf(xv.z, wcol[d + 2], a);  c = fmaf(xv.z, wcol[DIN + d + 2], c);
        a = fmaf(xv.w, wcol[d + 3], a);  c = fmaf(xv.w, wcol[DIN + d + 3], c);
    }
    g_At[k * BDIM + tid] = a;
    g_Ct[k * BDIM + tid] = c;

    // --- bitonic sort ascending across tid (value in register) ---
    float v = c;
    for (int size = 2; size <= BDIM; size <<= 1) {
        for (int stride = size >> 1; stride > 0; stride >>= 1) {
            float other;
            if (stride >= 32) {
                sc[tid] = v;
                __syncthreads();
                other = sc[tid ^ stride];
                __syncthreads();
            } else {
                other = __shfl_xor_sync(0xffffffffu, v, stride);
            }
            const bool up = ((tid & size) == 0);
            const bool lower = ((tid & stride) == 0);
            const float mn = fminf(v, other);
            const float mx = fmaxf(v, other);
            v = (up == lower) ? mn : mx;
        }
    }
    sc[tid] = v;   // sorted ascending

    // --- inclusive suffix sums of v, v^2 ---
    float w1 = v, w2 = v * v;
#pragma unroll
    for (int o = 1; o < 32; o <<= 1) {
        const float t1 = __shfl_down_sync(0xffffffffu, w1, o);
        const float t2 = __shfl_down_sync(0xffffffffu, w2, o);
        if (lane + o < 32) { w1 += t1; w2 += t2; }
    }
    if (lane == 0) { wr1[warp] = w1; wr2[warp] = w2; }
    __syncthreads();
    if (warp == 0) {
        const float o1 = wr1[lane];
        const float o2 = wr2[lane];
        float i1 = o1, i2 = o2;
#pragma unroll
        for (int o = 1; o < 32; o <<= 1) {
            const float t1 = __shfl_down_sync(0xffffffffu, i1, o);
            const float t2 = __shfl_down_sync(0xffffffffu, i2, o);
            if (lane + o < 32) { i1 += t1; i2 += t2; }
        }
        wr1[lane] = i1 - o1;   // exclusive suffix over later warps
        wr2[lane] = i2 - o2;
    }
    __syncthreads();
    ssf[tid]  = w1 + wr1[warp];
    ssf2[tid] = w2 + wr2[warp];
    if (tid == 0) { ssf[BDIM] = 0.f; ssf2[BDIM] = 0.f; }
    __syncthreads();

    // --- binary-search stats (thread's own 'a' register is the i value) ---
    const float th = -a;
    int lo = 0, hi = BDIM;
#pragma unroll
    for (int it = 0; it < 10; it++) {
        const int mid = (lo + hi) >> 1;
        if (sc[mid] > th) hi = mid; else lo = mid + 1;
        hi = (lo < hi) ? hi : lo;
        lo = (lo < hi) ? lo : hi;
    }
    const float n  = (float)(BDIM - lo);
    const float s1 = ssf[lo];
    const float s2 = ssf2[lo];
    float S = fmaf(n, a, s1);
    float Q = fmaf(n * a, a, fmaf(2.f * a, s1, s2));

#pragma unroll
    for (int o = 16; o > 0; o >>= 1) {
        S += __shfl_xor_sync(0xffffffffu, S, o);
        Q += __shfl_xor_sync(0xffffffffu, Q, o);
    }
    __syncthreads();
    if (lane == 0) { wr1[warp] = S; wr2[warp] = Q; }
    __syncthreads();
    if (tid == 0) {
        float St = 0.f, Qt = 0.f;
#pragma unroll
        for (int w = 0; w < 32; w++) { St += wr1[w]; Qt += wr2[w]; }
        const float N = (float)BDIM * (float)BDIM;
        const float mean = St / N;
        const float var  = Qt / N - mean * mean;
        const float rs   = rsqrtf(var + BN_EPS);
        const float wk   = W2[k];
        g_s[k] = gamma[k] * rs * wk;
        g_tpart[k] = (beta[k] - mean * rs * gamma[k]) * wk;
    }
}

// ---------------------------------------------------------------------------
// Kernel 2 (dominant): out[i][j] = t + P_i + R_j + sum_k (s_k/2)|At[k][i]+Ct[k][j]|
// 64x64 tile per block, 512 threads (16 warps), 4i x 2j per thread, packed
// f32x2 math with accumulators packed along i.  P/R/t computed inline.
// ---------------------------------------------------------------------------
__global__ __launch_bounds__(512) void pass2_kernel(
    const float* __restrict__ b2, float* __restrict__ out)
{
    __shared__ float As[64][64];              // [kk][i]
    __shared__ float Cs[64][64];              // [kk][j]
    __shared__ unsigned long long s2h[DHID];  // (s/2, s/2) packed
    __shared__ float ssc[DHID];
    __shared__ float Ps[64];
    __shared__ float Rs[64];
    __shared__ float tsh;

    const int i0 = blockIdx.y * 64;
    const int j0 = blockIdx.x * 64;
    const int tid = threadIdx.x;

    if (tid < DHID) {
        const float sv = g_s[tid];
        ssc[tid] = sv;
        const float sh = 0.5f * sv;
        unsigned long long p;
        asm("mov.b64 %0, {%1, %1};" : "=l"(p) : "f"(sh));
        s2h[tid] = p;
    }
    __syncthreads();

    // inline P / R / t (threads 0..159; others fall through to tile load sync)
    if (tid < 64) {
        float acc = 0.f;
#pragma unroll 16
        for (int k = 0; k < DHID; k++)
            acc = fmaf(ssc[k], g_At[k * BDIM + i0 + tid], acc);
        Ps[tid] = 0.5f * acc;
    } else if (tid < 128) {
        float acc = 0.f;
#pragma unroll 16
        for (int k = 0; k < DHID; k++)
            acc = fmaf(ssc[k], g_Ct[k * BDIM + j0 + tid - 64], acc);
        Rs[tid - 64] = 0.5f * acc;
    } else if (tid < 160) {
        const int l = tid - 128;
        float vv = g_tpart[l] + g_tpart[l + 32] + g_tpart[l + 64] + g_tpart[l + 96];
#pragma unroll
        for (int o = 16; o > 0; o >>= 1)
            vv += __shfl_xor_sync(0xffffffffu, vv, o);
        if (l == 0) tsh = vv + b2[0];
    }

    const int ty = tid >> 5;   // 0..15 -> i sub-tile of 4
    const int tx = tid & 31;   // 0..31 -> j sub-tile of 2

    unsigned long long acc2[2][2];   // [jp][ipair]
    acc2[0][0] = acc2[0][1] = acc2[1][0] = acc2[1][1] = 0ull;
    const unsigned long long MASK = 0x7FFFFFFF7FFFFFFFull;

    for (int kc = 0; kc < 2; kc++) {
        __syncthreads();
        for (int e = tid; e < 64 * 16; e += 512) {
            const int kk = e >> 4, vv = e & 15;
            const int kg = kc * 64 + kk;
            *(float4*)&As[kk][vv * 4] = *(const float4*)&g_At[kg * BDIM + i0 + vv * 4];
            *(float4*)&Cs[kk][vv * 4] = *(const float4*)&g_Ct[kg * BDIM + j0 + vv * 4];
        }
        __syncthreads();

#pragma unroll 8
        for (int kk = 0; kk < 64; kk++) {
            const ulonglong2 a2 = *(const ulonglong2*)&As[kk][ty * 4];   // (i0,i1),(i2,i3)
            const float2 cf = *(const float2*)&Cs[kk][tx * 2];
            const unsigned long long sk = s2h[kc * 64 + kk];
            unsigned long long cj[2];
            asm("mov.b64 %0, {%1, %1};" : "=l"(cj[0]) : "f"(cf.x));
            asm("mov.b64 %0, {%1, %1};" : "=l"(cj[1]) : "f"(cf.y));
#pragma unroll
            for (int jp = 0; jp < 2; jp++) {
#pragma unroll
                for (int ip = 0; ip < 2; ip++) {
                    const unsigned long long av = ip ? a2.y : a2.x;
                    unsigned long long vs;
                    asm("add.rn.f32x2 %0, %1, %2;" : "=l"(vs) : "l"(av), "l"(cj[jp]));
                    vs &= MASK;   // |.| on both packed lanes
                    asm("fma.rn.f32x2 %0, %1, %2, %3;"
                        : "=l"(acc2[jp][ip]) : "l"(vs), "l"(sk), "l"(acc2[jp][ip]));
                }
            }
        }
    }

    const float t = tsh;
#pragma unroll
    for (int ip = 0; ip < 2; ip++) {
        float v0j0, v1j0, v0j1, v1j1;
        asm("mov.b64 {%0, %1}, %2;" : "=f"(v0j0), "=f"(v1j0) : "l"(acc2[0][ip]));
        asm("mov.b64 {%0, %1}, %2;" : "=f"(v0j1), "=f"(v1j1) : "l"(acc2[1][ip]));
        const float r0 = Rs[tx * 2 + 0];
        const float r1 = Rs[tx * 2 + 1];
        const int ia = i0 + ty * 4 + ip * 2;
        const float pa = Ps[ty * 4 + ip * 2] + t;
        const float pb = Ps[ty * 4 + ip * 2 + 1] + t;
        float2 oa, ob;
        oa.x = v0j0 + pa + r0;  oa.y = v0j1 + pa + r1;
        ob.x = v1j0 + pb + r0;  ob.y = v1j1 + pb + r1;
        *(float2*)&out[(size_t)ia * BDIM + j0 + tx * 2] = oa;
        *(float2*)&out[(size_t)(ia + 1) * BDIM + j0 + tx * 2] = ob;
    }
}

// ---------------------------------------------------------------------------
extern "C" void kernel_launch(void* const* d_in, const int* in_sizes, int n_in,
                              void* d_out, int out_size)
{
    const float* x     = (const float*)d_in[0];
    const float* W1    = (const float*)d_in[1];
    const float* b1    = (const float*)d_in[2];
    const float* gamma = (const float*)d_in[3];
    const float* beta  = (const float*)d_in[4];
    const float* W2    = (const float*)d_in[5];
    const float* b2    = (const float*)d_in[6];
    float* out = (float*)d_out;

    channel_kernel<<<DHID, 1024>>>(x, W1, b1, gamma, beta, W2);
    pass2_kernel<<<dim3(16, 16), 512>>>(b2, out);
}

// round 4
// speedup vs baseline: 1.0450x; 1.0450x over previous
#include <cuda_runtime.h>
#include <cuda_bf16.h>
#include <cstdint>

// Problem constants
#define BDIM 1024
#define DIN  64
#define DHID 128
#define BN_EPS 1e-5f

typedef unsigned long long u64;

// Scratch (device globals; no allocations allowed)
__device__ float g_At[DHID * BDIM];   // A^T: [k][i] = b1[k] + sum_d x[i][d] W1[d][k]
__device__ float g_Ct[DHID * BDIM];   // C^T: [k][j] = sum_d x[j][d] W1[64+d][k]
__device__ float g_s[DHID];           // folded scale  gamma*rsigma*W2
__device__ float g_tpart[DHID];       // per-channel bias contribution

// ---------------------------------------------------------------------------
// Kernel 1 (fused): one block per channel k (128 blocks x 1024 threads).
//  - compute At[k][j], Ct[k][j] (thread j)
//  - register bitonic sort of Ct row, shfl suffix scans of c and c^2
//  - binary-search stats  ->  per-channel BN fold (g_s, g_tpart)
// ---------------------------------------------------------------------------
__global__ __launch_bounds__(1024) void channel_kernel(
    const float* __restrict__ x, const float* __restrict__ W1,
    const float* __restrict__ b1, const float* __restrict__ gamma,
    const float* __restrict__ beta, const float* __restrict__ W2)
{
    __shared__ float wcol[2 * DIN];
    __shared__ float sc[BDIM];
    __shared__ float ssf[BDIM + 2];
    __shared__ float ssf2[BDIM + 2];
    __shared__ float wr1[32];
    __shared__ float wr2[32];

    const int k = blockIdx.x;
    const int tid = threadIdx.x;
    const int lane = tid & 31;
    const int warp = tid >> 5;

    if (tid < 2 * DIN) wcol[tid] = W1[tid * DHID + k];
    __syncthreads();

    float a = b1[k], c = 0.f;
    const float4* xr = (const float4*)(x + (size_t)tid * DIN);
#pragma unroll
    for (int d4 = 0; d4 < DIN / 4; d4++) {
        const float4 xv = xr[d4];
        const int d = d4 * 4;
        a = fmaf(xv.x, wcol[d + 0], a);  c = fmaf(xv.x, wcol[DIN + d + 0], c);
        a = fmaf(xv.y, wcol[d + 1], a);  c = fmaf(xv.y, wcol[DIN + d + 1], c);
        a = fmaf(xv.z, wcol[d + 2], a);  c = fmaf(xv.z, wcol[DIN + d + 2], c);
        a = fmaf(xv.w, wcol[d + 3], a);  c = fmaf(xv.w, wcol[DIN + d + 3], c);
    }
    g_At[k * BDIM + tid] = a;
    g_Ct[k * BDIM + tid] = c;

    // --- bitonic sort ascending across tid ---
    float v = c;
    for (int size = 2; size <= BDIM; size <<= 1) {
        for (int stride = size >> 1; stride > 0; stride >>= 1) {
            float other;
            if (stride >= 32) {
                sc[tid] = v;
                __syncthreads();
                other = sc[tid ^ stride];
                __syncthreads();
            } else {
                other = __shfl_xor_sync(0xffffffffu, v, stride);
            }
            const bool up = ((tid & size) == 0);
            const bool lower = ((tid & stride) == 0);
            const float mn = fminf(v, other);
            const float mx = fmaxf(v, other);
            v = (up == lower) ? mn : mx;
        }
    }
    sc[tid] = v;

    // --- inclusive suffix sums of v, v^2 ---
    float w1 = v, w2 = v * v;
#pragma unroll
    for (int o = 1; o < 32; o <<= 1) {
        const float t1 = __shfl_down_sync(0xffffffffu, w1, o);
        const float t2 = __shfl_down_sync(0xffffffffu, w2, o);
        if (lane + o < 32) { w1 += t1; w2 += t2; }
    }
    if (lane == 0) { wr1[warp] = w1; wr2[warp] = w2; }
    __syncthreads();
    if (warp == 0) {
        const float o1 = wr1[lane];
        const float o2 = wr2[lane];
        float i1 = o1, i2 = o2;
#pragma unroll
        for (int o = 1; o < 32; o <<= 1) {
            const float t1 = __shfl_down_sync(0xffffffffu, i1, o);
            const float t2 = __shfl_down_sync(0xffffffffu, i2, o);
            if (lane + o < 32) { i1 += t1; i2 += t2; }
        }
        wr1[lane] = i1 - o1;
        wr2[lane] = i2 - o2;
    }
    __syncthreads();
    ssf[tid]  = w1 + wr1[warp];
    ssf2[tid] = w2 + wr2[warp];
    if (tid == 0) { ssf[BDIM] = 0.f; ssf2[BDIM] = 0.f; }
    __syncthreads();

    // --- binary-search stats ---
    const float th = -a;
    int lo = 0, hi = BDIM;
#pragma unroll
    for (int it = 0; it < 10; it++) {
        const int mid = (lo + hi) >> 1;
        if (sc[mid] > th) hi = mid; else lo = mid + 1;
        hi = (lo < hi) ? hi : lo;
        lo = (lo < hi) ? lo : hi;
    }
    const float n  = (float)(BDIM - lo);
    const float s1 = ssf[lo];
    const float s2 = ssf2[lo];
    float S = fmaf(n, a, s1);
    float Q = fmaf(n * a, a, fmaf(2.f * a, s1, s2));

#pragma unroll
    for (int o = 16; o > 0; o >>= 1) {
        S += __shfl_xor_sync(0xffffffffu, S, o);
        Q += __shfl_xor_sync(0xffffffffu, Q, o);
    }
    __syncthreads();
    if (lane == 0) { wr1[warp] = S; wr2[warp] = Q; }
    __syncthreads();
    if (tid == 0) {
        float St = 0.f, Qt = 0.f;
#pragma unroll
        for (int w = 0; w < 32; w++) { St += wr1[w]; Qt += wr2[w]; }
        const float N = (float)BDIM * (float)BDIM;
        const float mean = St / N;
        const float var  = Qt / N - mean * mean;
        const float rs   = rsqrtf(var + BN_EPS);
        const float wk   = W2[k];
        g_s[k] = gamma[k] * rs * wk;
        g_tpart[k] = (beta[k] - mean * rs * gamma[k]) * wk;
    }
}

// ---------------------------------------------------------------------------
// Kernel 2 (dominant): out[i][j] = t + P_i + R_j + sum_k (s_k/2)|At[k][i]+Ct[k][j]|
// 64x64 tile, 256 threads, 4i x 4j per thread, accumulators pack 2 j's.
// Full 128-k tiles in dynamic smem; A tile pre-splatted (a,a) pairs so no
// in-loop MOV splats.  P/R/t computed from the smem tiles in the prologue.
// ---------------------------------------------------------------------------
// dynamic smem layout (bytes)
#define AS2_OFF 0               // 128 * 64 * 8  = 65536   (a,a) pairs, row pitch 512B
#define CS_OFF  65536           // 128 * 64 * 4  = 32768   c floats, row pitch 256B
#define S2H_OFF 98304           // 128 * 8 (s/2,s/2)
#define SSC_OFF 99328           // 128 * 4 scalar s
#define PS_OFF  99840           // 64 * 4
#define RS_OFF  100096          // 64 * 4
#define PP_OFF  100352          // 4 * 64 * 4
#define RP_OFF  101376          // 4 * 64 * 4
#define TSH_OFF 102400          // 4
#define SMEM_BYTES 102464

__global__ __launch_bounds__(256) void pass2_kernel(
    const float* __restrict__ b2, float* __restrict__ out)
{
    extern __shared__ char smem[];
    char* sm_as2 = smem + AS2_OFF;
    char* sm_cs  = smem + CS_OFF;
    u64*  s2h    = (u64*)(smem + S2H_OFF);
    float* ssc   = (float*)(smem + SSC_OFF);
    float* Ps    = (float*)(smem + PS_OFF);
    float* Rs    = (float*)(smem + RS_OFF);
    float* Pp    = (float*)(smem + PP_OFF);
    float* Rp    = (float*)(smem + RP_OFF);
    float* tsh   = (float*)(smem + TSH_OFF);

    const int i0 = blockIdx.y * 64;
    const int j0 = blockIdx.x * 64;
    const int tid = threadIdx.x;

    // --- load scales ---
    if (tid < DHID) {
        const float sv = g_s[tid];
        ssc[tid] = sv;
        u64 p;
        asm("mov.b64 %0, {%1, %1};" : "=l"(p) : "f"(0.5f * sv));
        s2h[tid] = p;
    }

    // --- load tiles: A pre-splatted, C plain ---
    for (int e = tid; e < 128 * 16; e += 256) {
        const int kk = e >> 4, v = e & 15;
        const float4 a = *(const float4*)&g_At[kk * BDIM + i0 + v * 4];
        const float4 c = *(const float4*)&g_Ct[kk * BDIM + j0 + v * 4];
        float4 lo, hi;
        lo.x = a.x; lo.y = a.x; lo.z = a.y; lo.w = a.y;
        hi.x = a.z; hi.y = a.z; hi.z = a.w; hi.w = a.w;
        *(float4*)(sm_as2 + kk * 512 + v * 32)      = lo;
        *(float4*)(sm_as2 + kk * 512 + v * 32 + 16) = hi;
        *(float4*)(sm_cs  + kk * 256 + v * 16)      = c;
    }
    __syncthreads();

    // --- P/R partials from smem tiles ---
    {
        const int i = tid & 63;
        const int kg = tid >> 6;
        float accP = 0.f, accR = 0.f;
#pragma unroll 8
        for (int kk = kg * 32; kk < kg * 32 + 32; kk++) {
            accP = fmaf(ssc[kk], *(const float*)(sm_as2 + kk * 512 + i * 8), accP);
            accR = fmaf(ssc[kk], *(const float*)(sm_cs  + kk * 256 + i * 4), accR);
        }
        Pp[kg * 64 + i] = accP;
        Rp[kg * 64 + i] = accR;
    }
    __syncthreads();
    if (tid < 64) {
        Ps[tid] = 0.5f * (Pp[tid] + Pp[64 + tid] + Pp[128 + tid] + Pp[192 + tid]);
    } else if (tid < 128) {
        const int j = tid - 64;
        Rs[j] = 0.5f * (Rp[j] + Rp[64 + j] + Rp[128 + j] + Rp[192 + j]);
    } else if (tid < 160) {
        const int l = tid - 128;
        float vv = g_tpart[l] + g_tpart[l + 32] + g_tpart[l + 64] + g_tpart[l + 96];
#pragma unroll
        for (int o = 16; o > 0; o >>= 1)
            vv += __shfl_xor_sync(0xffffffffu, vv, o);
        if (l == 0) tsh[0] = vv + b2[0];
    }
    __syncthreads();

    const int ty = tid >> 4;   // 0..15 -> i sub-tile of 4
    const int tx = tid & 15;   // 0..15 -> j sub-tile of 4

    u64 acc2[4][2];   // [i][jpair]
#pragma unroll
    for (int q = 0; q < 4; q++) { acc2[q][0] = 0ull; acc2[q][1] = 0ull; }
    const u64 MASK = 0x7FFFFFFF7FFFFFFFull;

    const char* pa = sm_as2 + ty * 32;
    const char* pc = sm_cs + tx * 16;

#pragma unroll 4
    for (int kk = 0; kk < 128; kk++) {
        const ulonglong2 a01 = *(const ulonglong2*)(pa + kk * 512);       // (a0,a0),(a1,a1)
        const ulonglong2 a23 = *(const ulonglong2*)(pa + kk * 512 + 16);  // (a2,a2),(a3,a3)
        const ulonglong2 cp  = *(const ulonglong2*)(pc + kk * 256);       // (c0,c1),(c2,c3)
        const u64 sk = s2h[kk];
        const u64 av[4] = {a01.x, a01.y, a23.x, a23.y};
        const u64 cj[2] = {cp.x, cp.y};
#pragma unroll
        for (int q = 0; q < 4; q++) {
#pragma unroll
            for (int r = 0; r < 2; r++) {
                u64 vs;
                asm("add.rn.f32x2 %0, %1, %2;" : "=l"(vs) : "l"(av[q]), "l"(cj[r]));
                vs &= MASK;   // |.| on both packed lanes
                asm("fma.rn.f32x2 %0, %1, %2, %3;"
                    : "=l"(acc2[q][r]) : "l"(vs), "l"(sk), "l"(acc2[q][r]));
            }
        }
    }

    const float t = tsh[0];
    const float r0 = Rs[tx * 4 + 0];
    const float r1 = Rs[tx * 4 + 1];
    const float r2 = Rs[tx * 4 + 2];
    const float r3 = Rs[tx * 4 + 3];
#pragma unroll
    for (int q = 0; q < 4; q++) {
        float v0, v1, v2, v3;
        asm("mov.b64 {%0, %1}, %2;" : "=f"(v0), "=f"(v1) : "l"(acc2[q][0]));
        asm("mov.b64 {%0, %1}, %2;" : "=f"(v2), "=f"(v3) : "l"(acc2[q][1]));
        const float base = t + Ps[ty * 4 + q];
        float4 o;
        o.x = v0 + base + r0;
        o.y = v1 + base + r1;
        o.z = v2 + base + r2;
        o.w = v3 + base + r3;
        *(float4*)&out[(size_t)(i0 + ty * 4 + q) * BDIM + j0 + tx * 4] = o;
    }
}

// ---------------------------------------------------------------------------
extern "C" void kernel_launch(void* const* d_in, const int* in_sizes, int n_in,
                              void* d_out, int out_size)
{
    const float* x     = (const float*)d_in[0];
    const float* W1    = (const float*)d_in[1];
    const float* b1    = (const float*)d_in[2];
    const float* gamma = (const float*)d_in[3];
    const float* beta  = (const float*)d_in[4];
    const float* W2    = (const float*)d_in[5];
    const float* b2    = (const float*)d_in[6];
    float* out = (float*)d_out;

    cudaFuncSetAttribute(pass2_kernel,
                         cudaFuncAttributeMaxDynamicSharedMemorySize, SMEM_BYTES);

    channel_kernel<<<DHID, 1024>>>(x, W1, b1, gamma, beta, W2);
    pass2_kernel<<<dim3(16, 16), 256, SMEM_BYTES>>>(b2, out);
}